// round 7
// baseline (speedup 1.0000x reference)
#include <cuda_runtime.h>
#include <cuda_bf16.h>
#include <cstdint>

// VanillaRNN via HMMA bf16-split (fp32 accum), cluster-local sync.
// B=256,T=1024,D=64,H=512,C=10 fp32.
// 128 CTAs = 16 clusters(8) ; cluster = one 16-row tile, CTA = 64-col slice.
// No grid-wide sync: h exchange is intra-cluster (global stores + cluster bar).
// 512 thr = 16 warps = 4 K-groups(144) x 4 col-groups(16).

#define T_SEQ  1024
#define B_DIM  256
#define D_IN   64
#define H_DIM  512
#define NCLS   10
#define KTOT   576
#define GRID   128
#define NTHR   512
#define TILE_R 16
#define TILE_C 64

#define PKB    1168            // row stride bytes: 576*2 + 16 pad

#define OFF_AH   0
#define OFF_AL   (OFF_AH + TILE_R * PKB)          // 18688
#define OFF_BH   (OFF_AL + TILE_R * PKB)          // 37376
#define OFF_BL   (OFF_BH + TILE_C * PKB)          // 112128
#define OFF_RED  (OFF_BL + TILE_C * PKB)          // 186880: 4*16*64 fp32
#define OFF_BIAS (OFF_RED + 16384)                // 203264
#define SMEM_SZ  (OFF_BIAS + 256 + 16)

__device__ __nv_bfloat16 g_xhi[(size_t)B_DIM * T_SEQ * D_IN];
__device__ __nv_bfloat16 g_xlo[(size_t)B_DIM * T_SEQ * D_IN];
__device__ __nv_bfloat16 g_Hhi[2][B_DIM][H_DIM];
__device__ __nv_bfloat16 g_Hlo[2][B_DIM][H_DIM];
__device__ float         g_hfin[B_DIM][H_DIM];

__device__ __forceinline__ uint32_t smem_u32(const void* p) {
    uint32_t a;
    asm("{ .reg .u64 t; cvta.to.shared.u64 t, %1; cvt.u32.u64 %0, t; }"
        : "=r"(a) : "l"(p));
    return a;
}

#define LDSM4(r0, r1, r2, r3, addr)                                        \
    asm volatile("ldmatrix.sync.aligned.m8n8.x4.shared.b16 "               \
                 "{%0,%1,%2,%3}, [%4];"                                    \
                 : "=r"(r0), "=r"(r1), "=r"(r2), "=r"(r3) : "r"(addr))
#define MMA16816(d, a0, a1, a2, a3, b0, b1)                                \
    asm volatile("mma.sync.aligned.m16n8k16.row.col.f32.bf16.bf16.f32 "    \
                 "{%0,%1,%2,%3}, {%4,%5,%6,%7}, {%8,%9}, {%0,%1,%2,%3};"   \
                 : "+f"(d[0]), "+f"(d[1]), "+f"(d[2]), "+f"(d[3])          \
                 : "r"(a0), "r"(a1), "r"(a2), "r"(a3), "r"(b0), "r"(b1))

#define CLUSTER_ARRIVE() \
    asm volatile("barrier.cluster.arrive.aligned;" ::: "memory")
#define CLUSTER_WAIT() \
    asm volatile("barrier.cluster.wait.aligned;" ::: "memory")

__global__ void __cluster_dims__(8, 1, 1) __launch_bounds__(NTHR, 1)
rnn_hmma_cluster_kernel(const float* __restrict__ x,
                        const float* __restrict__ Whx,
                        const float* __restrict__ Whh,
                        const float* __restrict__ Wph,
                        const float* __restrict__ bh,
                        const float* __restrict__ bp,
                        float* __restrict__ out)
{
    extern __shared__ __align__(16) char smg[];
    const uint32_t sb = smem_u32(smg);

    const int tid  = threadIdx.x;
    const int wid  = tid >> 5;
    const int lane = tid & 31;
    const int bid  = blockIdx.x;
    const int jt   = bid & 7;            // col slice == cluster rank
    const int it   = bid >> 3;           // row tile == cluster id
    const int c0   = jt * TILE_C;
    const int r0   = it * TILE_R;

    float* sBias = reinterpret_cast<float*>(smg + OFF_BIAS);
    float* sRed  = reinterpret_cast<float*>(smg + OFF_RED);

    // ---- one-time: W slice -> SMEM bf16 hi/lo, padded rows [n][k] ----
    for (int i = tid; i < TILE_C * KTOT; i += NTHR) {
        const int n = i / KTOT, k = i - n * KTOT;
        const float w = (k < D_IN) ? Whx[k * H_DIM + c0 + n]
                                   : Whh[(k - D_IN) * H_DIM + c0 + n];
        const __nv_bfloat16 h16 = __float2bfloat16(w);
        const __nv_bfloat16 l16 = __float2bfloat16(w - __bfloat162float(h16));
        *reinterpret_cast<__nv_bfloat16*>(smg + OFF_BH + n * PKB + k * 2) = h16;
        *reinterpret_cast<__nv_bfloat16*>(smg + OFF_BL + n * PKB + k * 2) = l16;
    }
    if (tid < TILE_C) sBias[tid] = bh[c0 + tid];

    // ---- prologue: split THIS cluster's x rows into bf16 hi/lo ----
    {
        const size_t gbase = (size_t)r0 * T_SEQ * D_IN / 4;   // float4 units
        const int    total = TILE_R * T_SEQ * D_IN / 4;       // 262144
        for (int i = jt * NTHR + tid; i < total; i += 8 * NTHR) {
            const float4 v = __ldg(reinterpret_cast<const float4*>(x) + gbase + i);
            const __nv_bfloat162 hA = __floats2bfloat162_rn(v.x, v.y);
            const __nv_bfloat162 hB = __floats2bfloat162_rn(v.z, v.w);
            const __nv_bfloat162 lA = __floats2bfloat162_rn(
                v.x - __bfloat162float(hA.x), v.y - __bfloat162float(hA.y));
            const __nv_bfloat162 lB = __floats2bfloat162_rn(
                v.z - __bfloat162float(hB.x), v.w - __bfloat162float(hB.y));
            const size_t o = gbase + i;
            reinterpret_cast<__nv_bfloat162*>(g_xhi)[2 * o]     = hA;
            reinterpret_cast<__nv_bfloat162*>(g_xhi)[2 * o + 1] = hB;
            reinterpret_cast<__nv_bfloat162*>(g_xlo)[2 * o]     = lA;
            reinterpret_cast<__nv_bfloat162*>(g_xlo)[2 * o + 1] = lB;
        }
    }
    CLUSTER_ARRIVE();
    CLUSTER_WAIT();

    // warp roles: kg = K-group (144 each), ng = 16-col group
    const int kg = wid >> 2;
    const int ng = wid & 3;
    const int kbase = kg * 144;

    // ldmatrix byte offsets
    const uint32_t aoff = (uint32_t)(lane & 15) * PKB
                        + (uint32_t)((lane >> 4) << 4)
                        + (uint32_t)kbase * 2;
    const uint32_t boff = (uint32_t)(ng * 16 + ((lane >> 4) << 3) + (lane & 7)) * PKB
                        + (uint32_t)(((lane >> 3) & 1) << 4)
                        + (uint32_t)kbase * 2;

    const uint32_t sAh = sb + OFF_AH, sAl = sb + OFF_AL;
    const uint32_t sBh = sb + OFF_BH, sBl = sb + OFF_BL;

    // epilogue mapping: thread -> 2 consecutive outputs
    const int erow = (tid * 2) >> 6;
    const int ecol = (tid * 2) & 63;

    // ---- stage A for t=0: x_0 plus h_0 (global zeros) ----
    for (int u = tid; u < 256; u += NTHR) {        // x part: 2x16x8 units
        const int half = u >> 7, uu = u & 127, r = uu >> 3, q = uu & 7;
        const __nv_bfloat16* src = (half ? g_xlo : g_xhi)
            + ((size_t)(r0 + r) * T_SEQ + 0) * D_IN + q * 8;
        *reinterpret_cast<uint4*>(smg + (half ? OFF_AL : OFF_AH) + r * PKB + q * 16)
            = __ldg(reinterpret_cast<const uint4*>(src));
    }
    for (int u = tid; u < 2048; u += NTHR) {       // h part: 2x16x64 units
        const int half = u >> 10, uu = u & 1023, r = uu >> 6, q = uu & 63;
        const __nv_bfloat16* src =
            (half ? &g_Hlo[0][0][0] : &g_Hhi[0][0][0])
            + (size_t)(r0 + r) * H_DIM + q * 8;
        *reinterpret_cast<uint4*>(smg + (half ? OFF_AL : OFF_AH)
                                  + r * PKB + (8 + q) * 16)
            = __ldcv(reinterpret_cast<const uint4*>(src));
    }

    for (int t = 0; t < T_SEQ; ++t) {
        __syncthreads();   // A staged

        // ---- warp GEMM: m16 x n16 x k144, 3-product bf16 split ----
        float acc[2][4] = {};
        #pragma unroll
        for (int s = 0; s < 9; ++s) {
            const uint32_t ka = (uint32_t)s * 32;
            uint32_t ah0, ah1, ah2, ah3, al0, al1, al2, al3;
            uint32_t bh0, bh1, bh2, bh3, bl0, bl1, bl2, bl3;
            LDSM4(ah0, ah1, ah2, ah3, sAh + aoff + ka);
            LDSM4(al0, al1, al2, al3, sAl + aoff + ka);
            LDSM4(bh0, bh1, bh2, bh3, sBh + boff + ka);
            LDSM4(bl0, bl1, bl2, bl3, sBl + boff + ka);
            MMA16816(acc[0], ah0, ah1, ah2, ah3, bh0, bh1);
            MMA16816(acc[0], al0, al1, al2, al3, bh0, bh1);
            MMA16816(acc[0], ah0, ah1, ah2, ah3, bl0, bl1);
            MMA16816(acc[1], ah0, ah1, ah2, ah3, bh2, bh3);
            MMA16816(acc[1], al0, al1, al2, al3, bh2, bh3);
            MMA16816(acc[1], ah0, ah1, ah2, ah3, bl2, bl3);
        }

        // ---- write split-K partials: sRed[kg][16][64] ----
        {
            float* rb = sRed + kg * 1024;
            const int gr0 = lane >> 2;
            #pragma unroll
            for (int g = 0; g < 2; ++g) {
                const int c = ng * 16 + g * 8 + (lane & 3) * 2;
                *reinterpret_cast<float2*>(rb + gr0 * 64 + c) =
                    make_float2(acc[g][0], acc[g][1]);
                *reinterpret_cast<float2*>(rb + (gr0 + 8) * 64 + c) =
                    make_float2(acc[g][2], acc[g][3]);
            }
        }
        __syncthreads();

        // ---- reduce 4 partials + bias + tanh -> h bf16 hi/lo -> global ----
        {
            const int base = tid * 2;
            float2 p0 = *reinterpret_cast<float2*>(sRed + base);
            float2 p1 = *reinterpret_cast<float2*>(sRed + 1024 + base);
            float2 p2 = *reinterpret_cast<float2*>(sRed + 2048 + base);
            float2 p3 = *reinterpret_cast<float2*>(sRed + 3072 + base);
            const float v0 = tanhf((p0.x + p1.x) + (p2.x + p3.x) + sBias[ecol]);
            const float v1 = tanhf((p0.y + p1.y) + (p2.y + p3.y) + sBias[ecol + 1]);

            const __nv_bfloat162 h01 = __floats2bfloat162_rn(v0, v1);
            const __nv_bfloat162 l01 = __floats2bfloat162_rn(
                v0 - __bfloat162float(h01.x), v1 - __bfloat162float(h01.y));

            const int row = r0 + erow, col = c0 + ecol;
            *reinterpret_cast<uint32_t*>(&g_Hhi[(t + 1) & 1][row][col]) =
                *reinterpret_cast<const uint32_t*>(&h01);
            *reinterpret_cast<uint32_t*>(&g_Hlo[(t + 1) & 1][row][col]) =
                *reinterpret_cast<const uint32_t*>(&l01);
            if (t == T_SEQ - 1)
                *reinterpret_cast<float2*>(&g_hfin[row][col]) =
                    make_float2(v0, v1);
        }

        // ---- cluster handoff (arrive releases our global h stores) ----
        CLUSTER_ARRIVE();
        if (t + 1 < T_SEQ) {
            // overlap: x part of t+1 (independent of peers)
            for (int u = tid; u < 256; u += NTHR) {
                const int half = u >> 7, uu = u & 127, r = uu >> 3, q = uu & 7;
                const __nv_bfloat16* src = (half ? g_xlo : g_xhi)
                    + ((size_t)(r0 + r) * T_SEQ + (t + 1)) * D_IN + q * 8;
                *reinterpret_cast<uint4*>(smg + (half ? OFF_AL : OFF_AH)
                                          + r * PKB + q * 16)
                    = __ldg(reinterpret_cast<const uint4*>(src));
            }
        }
        CLUSTER_WAIT();
        if (t + 1 < T_SEQ) {
            const __nv_bfloat16* hbh = &g_Hhi[(t + 1) & 1][0][0];
            const __nv_bfloat16* hbl = &g_Hlo[(t + 1) & 1][0][0];
            for (int u = tid; u < 2048; u += NTHR) {
                const int half = u >> 10, uu = u & 1023, r = uu >> 6, q = uu & 63;
                const __nv_bfloat16* src = (half ? hbl : hbh)
                    + (size_t)(r0 + r) * H_DIM + q * 8;
                *reinterpret_cast<uint4*>(smg + (half ? OFF_AL : OFF_AH)
                                          + r * PKB + (8 + q) * 16)
                    = __ldcv(reinterpret_cast<const uint4*>(src));
            }
        }
    }

    // ---- final projection p = h_final @ Wph + bp (rank-0 CTAs) ----
    if (jt == 0) {
        float* sW = reinterpret_cast<float*>(smg + OFF_BH);   // 5120 floats
        float* sH = reinterpret_cast<float*>(smg + OFF_AH);   // 16x512
        for (int i = tid; i < H_DIM * NCLS; i += NTHR)
            sW[i] = Wph[i];
        for (int i = tid; i < TILE_R * H_DIM; i += NTHR) {
            const int r = i >> 9, k = i & 511;
            sH[r * H_DIM + k] = __ldcv(&g_hfin[r0 + r][k]);
        }
        __syncthreads();
        for (int i = tid; i < TILE_R * NCLS; i += NTHR) {
            const int r = i / NCLS, cc = i - (i / NCLS) * NCLS;
            float s = bp[cc];
            const float* hr = sH + r * H_DIM;
            #pragma unroll 8
            for (int k = 0; k < H_DIM; ++k)
                s += hr[k] * sW[k * NCLS + cc];
            out[(r0 + r) * NCLS + cc] = s;
        }
    }
}

extern "C" void kernel_launch(void* const* d_in, const int* in_sizes, int n_in,
                              void* d_out, int out_size)
{
    const float* x   = (const float*)d_in[0];
    const float* Whx = (const float*)d_in[1];
    const float* Whh = (const float*)d_in[2];
    const float* Wph = (const float*)d_in[3];
    const float* bh  = (const float*)d_in[4];
    const float* bp  = (const float*)d_in[5];
    float* out = (float*)d_out;

    // Deterministic per-launch state: zero h_0 (buffer 0, hi+lo).
    void *hhi_a = nullptr, *hlo_a = nullptr;
    cudaGetSymbolAddress(&hhi_a, g_Hhi);
    cudaGetSymbolAddress(&hlo_a, g_Hlo);
    cudaMemsetAsync(hhi_a, 0, (size_t)B_DIM * H_DIM * sizeof(__nv_bfloat16));
    cudaMemsetAsync(hlo_a, 0, (size_t)B_DIM * H_DIM * sizeof(__nv_bfloat16));

    cudaFuncSetAttribute(rnn_hmma_cluster_kernel,
                         cudaFuncAttributeMaxDynamicSharedMemorySize, SMEM_SZ);

    rnn_hmma_cluster_kernel<<<GRID, NTHR, SMEM_SZ>>>(
        x, Whx, Whh, Wph, bh, bp, out);
}

// round 8
// speedup vs baseline: 1.5636x; 1.5636x over previous
#include <cuda_runtime.h>
#include <cuda_bf16.h>
#include <cstdint>

// VanillaRNN via HMMA bf16-split (fp32 accum). B=256,T=1024,D=64,H=512,C=10.
// 128 CTAs = 16 row-tiles(16 rows) x 8 col-slices(64 cols), 512 threads.
// Sync: per-row-tile software barrier (8 arrivals on a private counter) --
// no grid-wide sync, no cluster HW barrier.
// Warps: 4 K-groups(144) x 4 col-groups(16); warp = m16 n16 k144, 3-product
// bf16-split MMA (hi*hi + lo*hi + hi*lo), fp32 accumulate.

#define T_SEQ  1024
#define B_DIM  256
#define D_IN   64
#define H_DIM  512
#define NCLS   10
#define KTOT   576
#define GRID   128
#define NTHR   512
#define TILE_R 16
#define TILE_C 64

#define PKB    1168            // row stride bytes: 576*2 + 16 pad

#define OFF_AH   0
#define OFF_AL   (OFF_AH + TILE_R * PKB)          // 18688
#define OFF_BH   (OFF_AL + TILE_R * PKB)          // 37376
#define OFF_BL   (OFF_BH + TILE_C * PKB)          // 112128
#define OFF_RED  (OFF_BL + TILE_C * PKB)          // 186880: 4*16*64 fp32
#define OFF_BIAS (OFF_RED + 16384)                // 203264
#define SMEM_SZ  (OFF_BIAS + 256 + 16)

__device__ __nv_bfloat16 g_xhi[(size_t)B_DIM * T_SEQ * D_IN];
__device__ __nv_bfloat16 g_xlo[(size_t)B_DIM * T_SEQ * D_IN];
__device__ __nv_bfloat16 g_Hhi[2][B_DIM][H_DIM];
__device__ __nv_bfloat16 g_Hlo[2][B_DIM][H_DIM];
__device__ float         g_hfin[B_DIM][H_DIM];
__device__ unsigned      g_bar[16 * 32];   // 1 counter per row-tile, 128B apart

__device__ __forceinline__ uint32_t smem_u32(const void* p) {
    uint32_t a;
    asm("{ .reg .u64 t; cvta.to.shared.u64 t, %1; cvt.u32.u64 %0, t; }"
        : "=r"(a) : "l"(p));
    return a;
}

#define LDSM4(r0, r1, r2, r3, addr)                                        \
    asm volatile("ldmatrix.sync.aligned.m8n8.x4.shared.b16 "               \
                 "{%0,%1,%2,%3}, [%4];"                                    \
                 : "=r"(r0), "=r"(r1), "=r"(r2), "=r"(r3) : "r"(addr))
#define MMA16816(d, a0, a1, a2, a3, b0, b1)                                \
    asm volatile("mma.sync.aligned.m16n8k16.row.col.f32.bf16.bf16.f32 "    \
                 "{%0,%1,%2,%3}, {%4,%5,%6,%7}, {%8,%9}, {%0,%1,%2,%3};"   \
                 : "+f"(d[0]), "+f"(d[1]), "+f"(d[2]), "+f"(d[3])          \
                 : "r"(a0), "r"(a1), "r"(a2), "r"(a3), "r"(b0), "r"(b1))

// Per-row-tile barrier: 8 CTAs arrive on a private counter; tid0 polls.
__device__ __forceinline__ void tile_barrier(int tid, int it, unsigned epoch) {
    __threadfence();
    __syncthreads();
    if (tid == 0) {
        atomicAdd(&g_bar[it * 32], 1u);
        while (*(volatile unsigned*)&g_bar[it * 32] < epoch * 8u) { }
        __threadfence();
    }
    __syncthreads();
}

__global__ void __launch_bounds__(NTHR, 1)
rnn_hmma16_kernel(const float* __restrict__ x,
                  const float* __restrict__ Whx,
                  const float* __restrict__ Whh,
                  const float* __restrict__ Wph,
                  const float* __restrict__ bh,
                  const float* __restrict__ bp,
                  float* __restrict__ out)
{
    extern __shared__ __align__(16) char smg[];
    const uint32_t sb = smem_u32(smg);

    const int tid  = threadIdx.x;
    const int wid  = tid >> 5;
    const int lane = tid & 31;
    const int bid  = blockIdx.x;
    const int jt   = bid & 7;            // col slice
    const int it   = bid >> 3;           // row tile
    const int c0   = jt * TILE_C;
    const int r0   = it * TILE_R;

    float* sBias = reinterpret_cast<float*>(smg + OFF_BIAS);
    float* sRed  = reinterpret_cast<float*>(smg + OFF_RED);

    // ---- one-time: W slice -> SMEM bf16 hi/lo, padded rows [n][k] ----
    for (int i = tid; i < TILE_C * KTOT; i += NTHR) {
        const int n = i / KTOT, k = i - n * KTOT;
        const float w = (k < D_IN) ? Whx[k * H_DIM + c0 + n]
                                   : Whh[(k - D_IN) * H_DIM + c0 + n];
        const __nv_bfloat16 h16 = __float2bfloat16(w);
        const __nv_bfloat16 l16 = __float2bfloat16(w - __bfloat162float(h16));
        *reinterpret_cast<__nv_bfloat16*>(smg + OFF_BH + n * PKB + k * 2) = h16;
        *reinterpret_cast<__nv_bfloat16*>(smg + OFF_BL + n * PKB + k * 2) = l16;
    }
    if (tid < TILE_C) sBias[tid] = bh[c0 + tid];

    // ---- prologue: split THIS row-tile's x rows into bf16 hi/lo ----
    {
        const size_t gbase = (size_t)r0 * T_SEQ * D_IN / 4;   // float4 units
        const int    total = TILE_R * T_SEQ * D_IN / 4;       // 262144
        for (int i = jt * NTHR + tid; i < total; i += 8 * NTHR) {
            const float4 v = __ldg(reinterpret_cast<const float4*>(x) + gbase + i);
            const __nv_bfloat162 hA = __floats2bfloat162_rn(v.x, v.y);
            const __nv_bfloat162 hB = __floats2bfloat162_rn(v.z, v.w);
            const __nv_bfloat162 lA = __floats2bfloat162_rn(
                v.x - __bfloat162float(hA.x), v.y - __bfloat162float(hA.y));
            const __nv_bfloat162 lB = __floats2bfloat162_rn(
                v.z - __bfloat162float(hB.x), v.w - __bfloat162float(hB.y));
            const size_t o = gbase + i;
            reinterpret_cast<__nv_bfloat162*>(g_xhi)[2 * o]     = hA;
            reinterpret_cast<__nv_bfloat162*>(g_xhi)[2 * o + 1] = hB;
            reinterpret_cast<__nv_bfloat162*>(g_xlo)[2 * o]     = lA;
            reinterpret_cast<__nv_bfloat162*>(g_xlo)[2 * o + 1] = lB;
        }
    }
    tile_barrier(tid, it, 1);

    // warp roles: kg = K-group (144 each), ng = 16-col group
    const int kg = wid >> 2;
    const int ng = wid & 3;
    const int kbase = kg * 144;

    const uint32_t aoff = (uint32_t)(lane & 15) * PKB
                        + (uint32_t)((lane >> 4) << 4)
                        + (uint32_t)kbase * 2;
    const uint32_t boff = (uint32_t)(ng * 16 + ((lane >> 4) << 3) + (lane & 7)) * PKB
                        + (uint32_t)(((lane >> 3) & 1) << 4)
                        + (uint32_t)kbase * 2;

    const uint32_t sAh = sb + OFF_AH, sAl = sb + OFF_AL;
    const uint32_t sBh = sb + OFF_BH, sBl = sb + OFF_BL;

    const int erow = (tid * 2) >> 6;
    const int ecol = (tid * 2) & 63;

    // ---- stage A for t=0: x_0 + h_0 (global zeros) ----
    for (int u = tid; u < 256; u += NTHR) {
        const int half = u >> 7, uu = u & 127, r = uu >> 3, q = uu & 7;
        const __nv_bfloat16* src = (half ? g_xlo : g_xhi)
            + ((size_t)(r0 + r) * T_SEQ + 0) * D_IN + q * 8;
        *reinterpret_cast<uint4*>(smg + (half ? OFF_AL : OFF_AH) + r * PKB + q * 16)
            = __ldg(reinterpret_cast<const uint4*>(src));
    }
    for (int u = tid; u < 2048; u += NTHR) {
        const int half = u >> 10, uu = u & 1023, r = uu >> 6, q = uu & 63;
        const __nv_bfloat16* src =
            (half ? &g_Hlo[0][0][0] : &g_Hhi[0][0][0])
            + (size_t)(r0 + r) * H_DIM + q * 8;
        *reinterpret_cast<uint4*>(smg + (half ? OFF_AL : OFF_AH)
                                  + r * PKB + (8 + q) * 16)
            = __ldcv(reinterpret_cast<const uint4*>(src));
    }

    for (int t = 0; t < T_SEQ; ++t) {
        __syncthreads();   // A staged

        // ---- warp GEMM: m16 x n16 x k144, 3-product bf16 split ----
        float acc[2][4] = {};
        #pragma unroll
        for (int s = 0; s < 9; ++s) {
            const uint32_t ka = (uint32_t)s * 32;
            uint32_t ah0, ah1, ah2, ah3, al0, al1, al2, al3;
            uint32_t bh0, bh1, bh2, bh3, bl0, bl1, bl2, bl3;
            LDSM4(ah0, ah1, ah2, ah3, sAh + aoff + ka);
            LDSM4(al0, al1, al2, al3, sAl + aoff + ka);
            LDSM4(bh0, bh1, bh2, bh3, sBh + boff + ka);
            LDSM4(bl0, bl1, bl2, bl3, sBl + boff + ka);
            MMA16816(acc[0], ah0, ah1, ah2, ah3, bh0, bh1);
            MMA16816(acc[0], al0, al1, al2, al3, bh0, bh1);
            MMA16816(acc[0], ah0, ah1, ah2, ah3, bl0, bl1);
            MMA16816(acc[1], ah0, ah1, ah2, ah3, bh2, bh3);
            MMA16816(acc[1], al0, al1, al2, al3, bh2, bh3);
            MMA16816(acc[1], ah0, ah1, ah2, ah3, bl2, bl3);
        }

        // ---- split-K partials -> sRed[kg][16][64] ----
        {
            float* rb = sRed + kg * 1024;
            const int gr0 = lane >> 2;
            #pragma unroll
            for (int g = 0; g < 2; ++g) {
                const int c = ng * 16 + g * 8 + (lane & 3) * 2;
                *reinterpret_cast<float2*>(rb + gr0 * 64 + c) =
                    make_float2(acc[g][0], acc[g][1]);
                *reinterpret_cast<float2*>(rb + (gr0 + 8) * 64 + c) =
                    make_float2(acc[g][2], acc[g][3]);
            }
        }
        __syncthreads();

        // ---- reduce + bias + tanh -> h bf16 hi/lo -> global ----
        {
            const int base = tid * 2;
            float2 p0 = *reinterpret_cast<float2*>(sRed + base);
            float2 p1 = *reinterpret_cast<float2*>(sRed + 1024 + base);
            float2 p2 = *reinterpret_cast<float2*>(sRed + 2048 + base);
            float2 p3 = *reinterpret_cast<float2*>(sRed + 3072 + base);
            const float v0 = tanhf((p0.x + p1.x) + (p2.x + p3.x) + sBias[ecol]);
            const float v1 = tanhf((p0.y + p1.y) + (p2.y + p3.y) + sBias[ecol + 1]);

            const __nv_bfloat162 h01 = __floats2bfloat162_rn(v0, v1);
            const __nv_bfloat162 l01 = __floats2bfloat162_rn(
                v0 - __bfloat162float(h01.x), v1 - __bfloat162float(h01.y));

            const int row = r0 + erow, col = c0 + ecol;
            *reinterpret_cast<uint32_t*>(&g_Hhi[(t + 1) & 1][row][col]) =
                *reinterpret_cast<const uint32_t*>(&h01);
            *reinterpret_cast<uint32_t*>(&g_Hlo[(t + 1) & 1][row][col]) =
                *reinterpret_cast<const uint32_t*>(&l01);
            if (t == T_SEQ - 1)
                *reinterpret_cast<float2*>(&g_hfin[row][col]) =
                    make_float2(v0, v1);
        }

        // ---- stage x part of t+1 (independent of peers) ----
        if (t + 1 < T_SEQ) {
            for (int u = tid; u < 256; u += NTHR) {
                const int half = u >> 7, uu = u & 127, r = uu >> 3, q = uu & 7;
                const __nv_bfloat16* src = (half ? g_xlo : g_xhi)
                    + ((size_t)(r0 + r) * T_SEQ + (t + 1)) * D_IN + q * 8;
                *reinterpret_cast<uint4*>(smg + (half ? OFF_AL : OFF_AH)
                                          + r * PKB + q * 16)
                    = __ldg(reinterpret_cast<const uint4*>(src));
            }
        }

        // ---- per-row-tile barrier, then stage h_{t+1} ----
        tile_barrier(tid, it, (unsigned)(t + 2));

        if (t + 1 < T_SEQ) {
            const __nv_bfloat16* hbh = &g_Hhi[(t + 1) & 1][0][0];
            const __nv_bfloat16* hbl = &g_Hlo[(t + 1) & 1][0][0];
            for (int u = tid; u < 2048; u += NTHR) {
                const int half = u >> 10, uu = u & 1023, r = uu >> 6, q = uu & 63;
                const __nv_bfloat16* src = (half ? hbl : hbh)
                    + (size_t)(r0 + r) * H_DIM + q * 8;
                *reinterpret_cast<uint4*>(smg + (half ? OFF_AL : OFF_AH)
                                          + r * PKB + (8 + q) * 16)
                    = __ldcv(reinterpret_cast<const uint4*>(src));
            }
        }
    }

    // ---- final projection p = h_final @ Wph + bp (col-slice-0 CTAs) ----
    if (jt == 0) {
        float* sW = reinterpret_cast<float*>(smg + OFF_BH);   // 5120 floats
        float* sH = reinterpret_cast<float*>(smg + OFF_AH);   // 16x512
        for (int i = tid; i < H_DIM * NCLS; i += NTHR)
            sW[i] = Wph[i];
        for (int i = tid; i < TILE_R * H_DIM; i += NTHR) {
            const int r = i >> 9, k = i & 511;
            sH[r * H_DIM + k] = __ldcv(&g_hfin[r0 + r][k]);
        }
        __syncthreads();
        for (int i = tid; i < TILE_R * NCLS; i += NTHR) {
            const int r = i / NCLS, cc = i - (i / NCLS) * NCLS;
            float s = bp[cc];
            const float* hr = sH + r * H_DIM;
            #pragma unroll 8
            for (int k = 0; k < H_DIM; ++k)
                s += hr[k] * sW[k * NCLS + cc];
            out[(r0 + r) * NCLS + cc] = s;
        }
    }
}

extern "C" void kernel_launch(void* const* d_in, const int* in_sizes, int n_in,
                              void* d_out, int out_size)
{
    const float* x   = (const float*)d_in[0];
    const float* Whx = (const float*)d_in[1];
    const float* Whh = (const float*)d_in[2];
    const float* Wph = (const float*)d_in[3];
    const float* bh  = (const float*)d_in[4];
    const float* bp  = (const float*)d_in[5];
    float* out = (float*)d_out;

    // Deterministic per-launch state: zero h_0 (buffer 0) + barrier counters.
    void *hhi_a = nullptr, *hlo_a = nullptr, *bar_a = nullptr;
    cudaGetSymbolAddress(&hhi_a, g_Hhi);
    cudaGetSymbolAddress(&hlo_a, g_Hlo);
    cudaGetSymbolAddress(&bar_a, g_bar);
    cudaMemsetAsync(hhi_a, 0, (size_t)B_DIM * H_DIM * sizeof(__nv_bfloat16));
    cudaMemsetAsync(hlo_a, 0, (size_t)B_DIM * H_DIM * sizeof(__nv_bfloat16));
    cudaMemsetAsync(bar_a, 0, 16 * 32 * sizeof(unsigned));

    cudaFuncSetAttribute(rnn_hmma16_kernel,
                         cudaFuncAttributeMaxDynamicSharedMemorySize, SMEM_SZ);

    rnn_hmma16_kernel<<<GRID, NTHR, SMEM_SZ>>>(x, Whx, Whh, Wph, bh, bp, out);
}